// round 14
// baseline (speedup 1.0000x reference)
#include <cuda_runtime.h>
#include <cuda_fp16.h>
#include <cstdint>

// Problem constants (from reference)
#define N_SRC   200000
#define D       128
#define N_RULES 250000
#define PERIOD  8

// fp16 copy of the gather table: 200000*128*2 = 51.2 MB (L2-resident w/ slack).
__device__ __half g_lv_h[(size_t)N_SRC * D];

// ---- cache-policy memory helpers -------------------------------------------

// Stream load: evict_first + 256B L2 prefetch (sequential streams).
__device__ __forceinline__ float4 ld_f4_stream(const float4* p, uint64_t pol)
{
    float4 v;
    asm volatile("ld.global.nc.L2::cache_hint.L2::256B.v4.f32 {%0,%1,%2,%3}, [%4], %5;"
                 : "=f"(v.x), "=f"(v.y), "=f"(v.z), "=f"(v.w)
                 : "l"(p), "l"(pol));
    return v;
}

// Gather load: 8 bytes, pinned in L2 via evict_last.
__device__ __forceinline__ void ld_u2_hint(const void* p, uint64_t pol,
                                           unsigned& a, unsigned& b)
{
    asm volatile("ld.global.nc.L2::cache_hint.v2.b32 {%0,%1}, [%2], %3;"
                 : "=r"(a), "=r"(b)
                 : "l"(p), "l"(pol));
}

__device__ __forceinline__ void st_u4_hint(void* p, unsigned a, unsigned b,
                                           unsigned c, unsigned d, uint64_t pol)
{
    asm volatile("st.global.L2::cache_hint.v4.b32 [%0], {%1,%2,%3,%4}, %5;"
                 :: "l"(p), "r"(a), "r"(b), "r"(c), "r"(d), "l"(pol)
                 : "memory");
}

// Output store: write-through — do NOT allocate/retain L2 lines for the
// 128 MB output stream; protects the pinned fp16 table from eviction.
__device__ __forceinline__ void st_wt_f4(float4* p, float4 v)
{
    asm volatile("st.global.wt.v4.f32 [%0], {%1,%2,%3,%4};"
                 :: "l"(p), "f"(v.x), "f"(v.y), "f"(v.z), "f"(v.w)
                 : "memory");
}

// ---- kernel 1: f32 -> fp16 table conversion --------------------------------
// Grid-strided, 2 chunks per thread (best measured config). Per chunk:
// read 32 B contiguous (2 x float4, evict_first + 256B prefetch), write one
// contiguous 16 B fp16 store (evict_last: pre-warm + pin in L2).
__global__ void __launch_bounds__(256)
convert_table_kernel(const float* __restrict__ layer_values)
{
    uint64_t pol_keep, pol_stream;
    asm volatile("createpolicy.fractional.L2::evict_last.b64 %0, 1.0;"  : "=l"(pol_keep));
    asm volatile("createpolicy.fractional.L2::evict_first.b64 %0, 1.0;" : "=l"(pol_stream));

    const size_t total8 = (size_t)N_SRC * D / 8;                 // 3,200,000 chunks
    const size_t stride = (size_t)gridDim.x * blockDim.x;        // chunks per pass
    size_t i = (size_t)blockIdx.x * blockDim.x + threadIdx.x;

#pragma unroll
    for (int pass = 0; pass < 2; ++pass, i += stride) {
        if (i < total8) {
            const float4* src = (const float4*)layer_values + i * 2;
            float4 v0 = ld_f4_stream(src,     pol_stream);
            float4 v1 = ld_f4_stream(src + 1, pol_stream);

            __half2 h0 = __floats2half2_rn(v0.x, v0.y);
            __half2 h1 = __floats2half2_rn(v0.z, v0.w);
            __half2 h2 = __floats2half2_rn(v1.x, v1.y);
            __half2 h3 = __floats2half2_rn(v1.z, v1.w);

            st_u4_hint((char*)g_lv_h + i * 16,
                       *reinterpret_cast<unsigned*>(&h0),
                       *reinterpret_cast<unsigned*>(&h1),
                       *reinterpret_cast<unsigned*>(&h2),
                       *reinterpret_cast<unsigned*>(&h3), pol_keep);
        }
    }
}

// ---- kernel 2: main weighted-rule kernel -----------------------------------
// One warp per rule (best measured DRAM saturation shape).
// Gather rows are fp16 (256 B/row = 32 lanes x 8 B); weights f32 float4/lane.
__global__ void __launch_bounds__(256, 8)
weighted_rule_kernel(const float* __restrict__ weights,
                     const int* __restrict__ indices,
                     float* __restrict__ out)
{
    const int warp_global = (blockIdx.x * blockDim.x + threadIdx.x) >> 5;
    const int lane = threadIdx.x & 31;
    if (warp_global >= N_RULES) return;

    uint64_t pol_keep, pol_stream;
    asm volatile("createpolicy.fractional.L2::evict_last.b64 %0, 1.0;"  : "=l"(pol_keep));
    asm volatile("createpolicy.fractional.L2::evict_first.b64 %0, 1.0;" : "=l"(pol_stream));

    // Lanes 0..7 load the 8 indices for this rule; broadcast via shfl.
    int my_idx = 0;
    if (lane < PERIOD) {
        my_idx = __ldg(indices + (size_t)warp_global * PERIOD + lane);
    }

    const float4* __restrict__ wbase =
        (const float4*)(weights + (size_t)warp_global * PERIOD * D);

    float4 acc = make_float4(0.f, 0.f, 0.f, 0.f);

#pragma unroll
    for (int p = 0; p < PERIOD; ++p) {
        int src = __shfl_sync(0xFFFFFFFFu, my_idx, p);

        // fp16 gather: lane owns columns [4*lane, 4*lane+4) -> 8 bytes.
        unsigned a, b;
        ld_u2_hint((const char*)g_lv_h + ((size_t)src * D + lane * 4) * 2, pol_keep, a, b);

        float4 w = ld_f4_stream(wbase + p * (D / 4) + lane, pol_stream);

        __half2 h;
        *reinterpret_cast<unsigned*>(&h) = a;
        float2 f01 = __half22float2(h);
        *reinterpret_cast<unsigned*>(&h) = b;
        float2 f23 = __half22float2(h);
        acc.x = fmaf(f01.x, w.x, acc.x);
        acc.y = fmaf(f01.y, w.y, acc.y);
        acc.z = fmaf(f23.x, w.z, acc.z);
        acc.w = fmaf(f23.y, w.w, acc.w);
    }

    float4 r;
    r.x = tanhf(acc.x);
    r.y = tanhf(acc.y);
    r.z = tanhf(acc.z);
    r.w = tanhf(acc.w);

    st_wt_f4(((float4*)(out + (size_t)warp_global * D)) + lane, r);
}

extern "C" void kernel_launch(void* const* d_in, const int* in_sizes, int n_in,
                              void* d_out, int out_size)
{
    const float* layer_values = (const float*)d_in[0];
    const float* weights      = (const float*)d_in[1];
    const int*   indices      = (const int*)d_in[2];
    float*       out          = (float*)d_out;

    // Kernel 1: build fp16 table. 3.2M chunks, 2 chunks/thread.
    {
        const int threads = 256;
        const int total8  = N_SRC * D / 8;            // 3,200,000
        const int threads_needed = (total8 + 1) / 2;  // 1,600,000
        const int blocks  = (threads_needed + threads - 1) / threads;
        convert_table_kernel<<<blocks, threads>>>(layer_values);
    }

    // Kernel 2: main compute, one warp per rule.
    {
        const int threads = 256;                      // 8 warps = 8 rules/block
        const int rules_per_block = threads / 32;
        const int blocks = (N_RULES + rules_per_block - 1) / rules_per_block;
        weighted_rule_kernel<<<blocks, threads>>>(weights, indices, out);
    }
}

// round 15
// speedup vs baseline: 1.0166x; 1.0166x over previous
#include <cuda_runtime.h>
#include <cuda_fp16.h>
#include <cstdint>

// Problem constants (from reference)
#define N_SRC   200000
#define D       128
#define N_RULES 250000
#define PERIOD  8

// fp16 copy of the gather table: 200000*128*2 = 51.2 MB (L2-resident w/ slack).
__device__ __half g_lv_h[(size_t)N_SRC * D];

// ---- cache-policy memory helpers -------------------------------------------

// Stream load: evict_first + 256B L2 prefetch (sequential streams).
__device__ __forceinline__ float4 ld_f4_stream(const float4* p, uint64_t pol)
{
    float4 v;
    asm volatile("ld.global.nc.L2::cache_hint.L2::256B.v4.f32 {%0,%1,%2,%3}, [%4], %5;"
                 : "=f"(v.x), "=f"(v.y), "=f"(v.z), "=f"(v.w)
                 : "l"(p), "l"(pol));
    return v;
}

// Gather load: 8 bytes, pinned in L2 via evict_last.
__device__ __forceinline__ void ld_u2_hint(const void* p, uint64_t pol,
                                           unsigned& a, unsigned& b)
{
    asm volatile("ld.global.nc.L2::cache_hint.v2.b32 {%0,%1}, [%2], %3;"
                 : "=r"(a), "=r"(b)
                 : "l"(p), "l"(pol));
}

__device__ __forceinline__ void st_u4_hint(void* p, unsigned a, unsigned b,
                                           unsigned c, unsigned d, uint64_t pol)
{
    asm volatile("st.global.L2::cache_hint.v4.b32 [%0], {%1,%2,%3,%4}, %5;"
                 :: "l"(p), "r"(a), "r"(b), "r"(c), "r"(d), "l"(pol)
                 : "memory");
}

// Output store: streaming write-back (evict-first). Measured best (r14 showed
// write-through regresses: it serializes the DRAM write path).
__device__ __forceinline__ void st_stream_f4(float4* p, float4 v)
{
    asm volatile("st.global.cs.v4.f32 [%0], {%1,%2,%3,%4};"
                 :: "l"(p), "f"(v.x), "f"(v.y), "f"(v.z), "f"(v.w)
                 : "memory");
}

// ---- kernel 1: f32 -> fp16 table conversion --------------------------------
// Grid-strided, 2 chunks per thread (best measured config). Per chunk:
// read 32 B contiguous (2 x float4, evict_first + 256B prefetch), write one
// contiguous 16 B fp16 store (evict_last: pre-warm + pin in L2).
__global__ void __launch_bounds__(256)
convert_table_kernel(const float* __restrict__ layer_values)
{
    uint64_t pol_keep, pol_stream;
    asm volatile("createpolicy.fractional.L2::evict_last.b64 %0, 1.0;"  : "=l"(pol_keep));
    asm volatile("createpolicy.fractional.L2::evict_first.b64 %0, 1.0;" : "=l"(pol_stream));

    const size_t total8 = (size_t)N_SRC * D / 8;                 // 3,200,000 chunks
    const size_t stride = (size_t)gridDim.x * blockDim.x;        // chunks per pass
    size_t i = (size_t)blockIdx.x * blockDim.x + threadIdx.x;

#pragma unroll
    for (int pass = 0; pass < 2; ++pass, i += stride) {
        if (i < total8) {
            const float4* src = (const float4*)layer_values + i * 2;
            float4 v0 = ld_f4_stream(src,     pol_stream);
            float4 v1 = ld_f4_stream(src + 1, pol_stream);

            __half2 h0 = __floats2half2_rn(v0.x, v0.y);
            __half2 h1 = __floats2half2_rn(v0.z, v0.w);
            __half2 h2 = __floats2half2_rn(v1.x, v1.y);
            __half2 h3 = __floats2half2_rn(v1.z, v1.w);

            st_u4_hint((char*)g_lv_h + i * 16,
                       *reinterpret_cast<unsigned*>(&h0),
                       *reinterpret_cast<unsigned*>(&h1),
                       *reinterpret_cast<unsigned*>(&h2),
                       *reinterpret_cast<unsigned*>(&h3), pol_keep);
        }
    }
}

// ---- kernel 2: main weighted-rule kernel -----------------------------------
// One warp per rule (best measured DRAM saturation shape).
// Gather rows are fp16 (256 B/row = 32 lanes x 8 B); weights f32 float4/lane.
__global__ void __launch_bounds__(256, 8)
weighted_rule_kernel(const float* __restrict__ weights,
                     const int* __restrict__ indices,
                     float* __restrict__ out)
{
    const int warp_global = (blockIdx.x * blockDim.x + threadIdx.x) >> 5;
    const int lane = threadIdx.x & 31;
    if (warp_global >= N_RULES) return;

    uint64_t pol_keep, pol_stream;
    asm volatile("createpolicy.fractional.L2::evict_last.b64 %0, 1.0;"  : "=l"(pol_keep));
    asm volatile("createpolicy.fractional.L2::evict_first.b64 %0, 1.0;" : "=l"(pol_stream));

    // Lanes 0..7 load the 8 indices for this rule; broadcast via shfl.
    int my_idx = 0;
    if (lane < PERIOD) {
        my_idx = __ldg(indices + (size_t)warp_global * PERIOD + lane);
    }

    const float4* __restrict__ wbase =
        (const float4*)(weights + (size_t)warp_global * PERIOD * D);

    float4 acc = make_float4(0.f, 0.f, 0.f, 0.f);

#pragma unroll
    for (int p = 0; p < PERIOD; ++p) {
        int src = __shfl_sync(0xFFFFFFFFu, my_idx, p);

        // fp16 gather: lane owns columns [4*lane, 4*lane+4) -> 8 bytes.
        unsigned a, b;
        ld_u2_hint((const char*)g_lv_h + ((size_t)src * D + lane * 4) * 2, pol_keep, a, b);

        float4 w = ld_f4_stream(wbase + p * (D / 4) + lane, pol_stream);

        __half2 h;
        *reinterpret_cast<unsigned*>(&h) = a;
        float2 f01 = __half22float2(h);
        *reinterpret_cast<unsigned*>(&h) = b;
        float2 f23 = __half22float2(h);
        acc.x = fmaf(f01.x, w.x, acc.x);
        acc.y = fmaf(f01.y, w.y, acc.y);
        acc.z = fmaf(f23.x, w.z, acc.z);
        acc.w = fmaf(f23.y, w.w, acc.w);
    }

    float4 r;
    r.x = tanhf(acc.x);
    r.y = tanhf(acc.y);
    r.z = tanhf(acc.z);
    r.w = tanhf(acc.w);

    st_stream_f4(((float4*)(out + (size_t)warp_global * D)) + lane, r);
}

extern "C" void kernel_launch(void* const* d_in, const int* in_sizes, int n_in,
                              void* d_out, int out_size)
{
    const float* layer_values = (const float*)d_in[0];
    const float* weights      = (const float*)d_in[1];
    const int*   indices      = (const int*)d_in[2];
    float*       out          = (float*)d_out;

    // Kernel 1: build fp16 table. 3.2M chunks, 2 chunks/thread.
    {
        const int threads = 256;
        const int total8  = N_SRC * D / 8;            // 3,200,000
        const int threads_needed = (total8 + 1) / 2;  // 1,600,000
        const int blocks  = (threads_needed + threads - 1) / threads;
        convert_table_kernel<<<blocks, threads>>>(layer_values);
    }

    // Kernel 2: main compute, one warp per rule.
    {
        const int threads = 256;                      // 8 warps = 8 rules/block
        const int rules_per_block = threads / 32;
        const int blocks = (N_RULES + rules_per_block - 1) / rules_per_block;
        weighted_rule_kernel<<<blocks, threads>>>(weights, indices, out);
    }
}

// round 17
// speedup vs baseline: 1.0252x; 1.0084x over previous
#include <cuda_runtime.h>
#include <cuda_fp16.h>
#include <cstdint>

// Problem constants (from reference)
#define N_SRC   200000
#define D       128
#define N_RULES 250000
#define PERIOD  8

// fp16 copy of the gather table: 200000*128*2 = 51.2 MB (L2-resident w/ slack).
__device__ __half g_lv_h[(size_t)N_SRC * D];

// ---- cache-policy memory helpers -------------------------------------------

// Stream load: evict_first + 256B L2 prefetch (sequential streams).
__device__ __forceinline__ float4 ld_f4_stream(const float4* p, uint64_t pol)
{
    float4 v;
    asm volatile("ld.global.nc.L2::cache_hint.L2::256B.v4.f32 {%0,%1,%2,%3}, [%4], %5;"
                 : "=f"(v.x), "=f"(v.y), "=f"(v.z), "=f"(v.w)
                 : "l"(p), "l"(pol));
    return v;
}

// Gather load: 8 bytes, pinned in L2 via evict_last.
__device__ __forceinline__ void ld_u2_hint(const void* p, uint64_t pol,
                                           unsigned& a, unsigned& b)
{
    asm volatile("ld.global.nc.L2::cache_hint.v2.b32 {%0,%1}, [%2], %3;"
                 : "=r"(a), "=r"(b)
                 : "l"(p), "l"(pol));
}

__device__ __forceinline__ void st_u4_hint(void* p, unsigned a, unsigned b,
                                           unsigned c, unsigned d, uint64_t pol)
{
    asm volatile("st.global.L2::cache_hint.v4.b32 [%0], {%1,%2,%3,%4}, %5;"
                 :: "l"(p), "r"(a), "r"(b), "r"(c), "r"(d), "l"(pol)
                 : "memory");
}

// Output store: streaming write-back (evict-first). Measured best (r14 showed
// write-through regresses: it serializes the DRAM write path).
__device__ __forceinline__ void st_stream_f4(float4* p, float4 v)
{
    asm volatile("st.global.cs.v4.f32 [%0], {%1,%2,%3,%4};"
                 :: "l"(p), "f"(v.x), "f"(v.y), "f"(v.z), "f"(v.w)
                 : "memory");
}

// ---- kernel 1: f32 -> fp16 table conversion --------------------------------
// Grid-strided, 2 chunks per thread (best measured config). Per chunk:
// read 32 B contiguous (2 x float4, evict_first + 256B prefetch), write one
// contiguous 16 B fp16 store (evict_last: pre-warm + pin in L2).
__global__ void __launch_bounds__(256)
convert_table_kernel(const float* __restrict__ layer_values)
{
    uint64_t pol_keep, pol_stream;
    asm volatile("createpolicy.fractional.L2::evict_last.b64 %0, 1.0;"  : "=l"(pol_keep));
    asm volatile("createpolicy.fractional.L2::evict_first.b64 %0, 1.0;" : "=l"(pol_stream));

    const size_t total8 = (size_t)N_SRC * D / 8;                 // 3,200,000 chunks
    const size_t stride = (size_t)gridDim.x * blockDim.x;        // chunks per pass
    size_t i = (size_t)blockIdx.x * blockDim.x + threadIdx.x;

#pragma unroll
    for (int pass = 0; pass < 2; ++pass, i += stride) {
        if (i < total8) {
            const float4* src = (const float4*)layer_values + i * 2;
            float4 v0 = ld_f4_stream(src,     pol_stream);
            float4 v1 = ld_f4_stream(src + 1, pol_stream);

            __half2 h0 = __floats2half2_rn(v0.x, v0.y);
            __half2 h1 = __floats2half2_rn(v0.z, v0.w);
            __half2 h2 = __floats2half2_rn(v1.x, v1.y);
            __half2 h3 = __floats2half2_rn(v1.z, v1.w);

            st_u4_hint((char*)g_lv_h + i * 16,
                       *reinterpret_cast<unsigned*>(&h0),
                       *reinterpret_cast<unsigned*>(&h1),
                       *reinterpret_cast<unsigned*>(&h2),
                       *reinterpret_cast<unsigned*>(&h3), pol_keep);
        }
    }
}

// ---- kernel 2: main weighted-rule kernel -----------------------------------
// One warp per rule (best measured DRAM saturation shape).
// Gather rows are fp16 (256 B/row = 32 lanes x 8 B); weights f32 float4/lane.
__global__ void __launch_bounds__(256, 8)
weighted_rule_kernel(const float* __restrict__ weights,
                     const int* __restrict__ indices,
                     float* __restrict__ out)
{
    const int warp_global = (blockIdx.x * blockDim.x + threadIdx.x) >> 5;
    const int lane = threadIdx.x & 31;
    if (warp_global >= N_RULES) return;

    uint64_t pol_keep, pol_stream;
    asm volatile("createpolicy.fractional.L2::evict_last.b64 %0, 1.0;"  : "=l"(pol_keep));
    asm volatile("createpolicy.fractional.L2::evict_first.b64 %0, 1.0;" : "=l"(pol_stream));

    // Lanes 0..7 load the 8 indices for this rule; broadcast via shfl.
    int my_idx = 0;
    if (lane < PERIOD) {
        my_idx = __ldg(indices + (size_t)warp_global * PERIOD + lane);
    }

    const float4* __restrict__ wbase =
        (const float4*)(weights + (size_t)warp_global * PERIOD * D);

    float4 acc = make_float4(0.f, 0.f, 0.f, 0.f);

#pragma unroll
    for (int p = 0; p < PERIOD; ++p) {
        int src = __shfl_sync(0xFFFFFFFFu, my_idx, p);

        // fp16 gather: lane owns columns [4*lane, 4*lane+4) -> 8 bytes.
        unsigned a, b;
        ld_u2_hint((const char*)g_lv_h + ((size_t)src * D + lane * 4) * 2, pol_keep, a, b);

        float4 w = ld_f4_stream(wbase + p * (D / 4) + lane, pol_stream);

        __half2 h;
        *reinterpret_cast<unsigned*>(&h) = a;
        float2 f01 = __half22float2(h);
        *reinterpret_cast<unsigned*>(&h) = b;
        float2 f23 = __half22float2(h);
        acc.x = fmaf(f01.x, w.x, acc.x);
        acc.y = fmaf(f01.y, w.y, acc.y);
        acc.z = fmaf(f23.x, w.z, acc.z);
        acc.w = fmaf(f23.y, w.w, acc.w);
    }

    float4 r;
    r.x = tanhf(acc.x);
    r.y = tanhf(acc.y);
    r.z = tanhf(acc.z);
    r.w = tanhf(acc.w);

    st_stream_f4(((float4*)(out + (size_t)warp_global * D)) + lane, r);
}

extern "C" void kernel_launch(void* const* d_in, const int* in_sizes, int n_in,
                              void* d_out, int out_size)
{
    const float* layer_values = (const float*)d_in[0];
    const float* weights      = (const float*)d_in[1];
    const int*   indices      = (const int*)d_in[2];
    float*       out          = (float*)d_out;

    // Kernel 1: build fp16 table. 3.2M chunks, 2 chunks/thread.
    {
        const int threads = 256;
        const int total8  = N_SRC * D / 8;            // 3,200,000
        const int threads_needed = (total8 + 1) / 2;  // 1,600,000
        const int blocks  = (threads_needed + threads - 1) / threads;
        convert_table_kernel<<<blocks, threads>>>(layer_values);
    }

    // Kernel 2: main compute, one warp per rule.
    {
        const int threads = 256;                      // 8 warps = 8 rules/block
        const int rules_per_block = threads / 32;
        const int blocks = (N_RULES + rules_per_block - 1) / rules_per_block;
        weighted_rule_kernel<<<blocks, threads>>>(weights, indices, out);
    }
}